// round 1
// baseline (speedup 1.0000x reference)
#include <cuda_runtime.h>
#include <cuda_bf16.h>

// Problem constants (fixed by the dataset's setup_inputs)
#define POOLED_H 7
#define POOLED_W 7
#define SPATIAL_SCALE 0.25f
#define SR 2            // sampling ratio
#define C_CH 256
#define H_FEAT 200
#define W_FEAT 272

__global__ void roi_align_kernel(const float* __restrict__ feat,
                                 const float* __restrict__ rois,
                                 float* __restrict__ out,
                                 int total, int n_rois) {
    int idx = blockIdx.x * blockDim.x + threadIdx.x;
    if (idx >= total) return;

    const int PW = POOLED_W, PH = POOLED_H;
    int pw = idx % PW;
    int ph = (idx / PW) % PH;
    int c  = (idx / (PW * PH)) % C_CH;
    int n  = idx / (PW * PH * C_CH);

    const float* r = rois + n * 5;
    int   b  = (int)r[0];
    float sw = r[1] * SPATIAL_SCALE;
    float sh = r[2] * SPATIAL_SCALE;
    float ew = r[3] * SPATIAL_SCALE;
    float eh = r[4] * SPATIAL_SCALE;

    float roi_w = fmaxf(ew - sw, 1.0f);
    float roi_h = fmaxf(eh - sh, 1.0f);
    float bin_w = roi_w / PW;
    float bin_h = roi_h / PH;

    const float* f = feat + ((long)b * C_CH + c) * (H_FEAT * W_FEAT);

    const float Hf = (float)H_FEAT;
    const float Wf = (float)W_FEAT;

    float acc = 0.0f;

    #pragma unroll
    for (int iy = 0; iy < SR; iy++) {
        float oy = ((float)(ph * SR + iy) + 0.5f) / (float)SR;
        float y  = sh + oy * bin_h;
        // valid iff y > -1 && y < H (reference semantics); invalid contributes 0
        if (!(y > -1.0f && y < Hf)) continue;
        float yc = fminf(fmaxf(y, 0.0f), Hf - 1.0f);
        int   yl = (int)floorf(yc);
        int   yh = min(yl + 1, H_FEAT - 1);
        float ly = yc - (float)yl;
        float hy = 1.0f - ly;

        #pragma unroll
        for (int ix = 0; ix < SR; ix++) {
            float ox = ((float)(pw * SR + ix) + 0.5f) / (float)SR;
            float x  = sw + ox * bin_w;
            if (!(x > -1.0f && x < Wf)) continue;
            float xc = fminf(fmaxf(x, 0.0f), Wf - 1.0f);
            int   xl = (int)floorf(xc);
            int   xh = min(xl + 1, W_FEAT - 1);
            float lx = xc - (float)xl;
            float hx = 1.0f - lx;

            float v00 = __ldg(&f[yl * W_FEAT + xl]);
            float v01 = __ldg(&f[yl * W_FEAT + xh]);
            float v10 = __ldg(&f[yh * W_FEAT + xl]);
            float v11 = __ldg(&f[yh * W_FEAT + xh]);

            acc += hy * hx * v00 + hy * lx * v01 + ly * hx * v10 + ly * lx * v11;
        }
    }

    out[idx] = acc * (1.0f / (SR * SR));
}

extern "C" void kernel_launch(void* const* d_in, const int* in_sizes, int n_in,
                              void* d_out, int out_size) {
    const float* feat = (const float*)d_in[0];
    const float* rois = (const float*)d_in[1];
    float* out = (float*)d_out;

    int n_rois = in_sizes[1] / 5;
    int total  = n_rois * C_CH * POOLED_H * POOLED_W;

    int threads = 256;
    int blocks  = (total + threads - 1) / threads;
    roi_align_kernel<<<blocks, threads>>>(feat, rois, out, total, n_rois);
}